// round 10
// baseline (speedup 1.0000x reference)
#include <cuda_runtime.h>
#include <cstdint>

#define LN_EPS 1e-5f
#define D_EPS  1e-6f
#define BATCH  16
#define SEQL   2048
#define NCHUNK 32           // 32 chunks x 64 steps = 2048 (2047 real + 1 pad)

// Scratch
__device__ float g_tab[64 * 64];
__device__ float g_G[64 * 64];                     // Gram
__device__ float g_TW[64 * 64];                    // Tab @ Wr
__device__ float g_rpos[64];                       // 1/(||tab||^2 + eps)
__device__ float g_dpos[64];                       // (||tab||^2 + eps)
// per chunk: [ Bc' (64x64) | Fc (64x64) ]  (8192 floats)
__device__ float g_BF[BATCH * NCHUNK * 8192];

// ---------------------------------------------------------------------------
__device__ __forceinline__ void cp_async16(uint32_t saddr, const void* gaddr) {
    asm volatile("cp.async.cg.shared.global [%0], [%1], 16;"
                 :: "r"(saddr), "l"(gaddr));
}
__device__ __forceinline__ void cp_commit() {
    asm volatile("cp.async.commit_group;");
}
__device__ __forceinline__ void cp_wait1() {
    asm volatile("cp.async.wait_group 1;");
}

// ---------------------------------------------------------------------------
// K1: per-token table, 16 blocks x 256 threads x 4 tokens, weights in smem.
// ---------------------------------------------------------------------------
#define TBL_SMEM_FLOATS 17184
#define TBL_SMEM_BYTES  (TBL_SMEM_FLOATS * 4)

__global__ __launch_bounds__(256) void table_kernel(
    const float* __restrict__ embed, const float* __restrict__ W1,
    const float* __restrict__ b1, const float* __restrict__ W2,
    const float* __restrict__ b2, const float* __restrict__ gamma,
    const float* __restrict__ beta)
{
    extern __shared__ float ts[];
    float* W1s  = ts;            // 8192
    float* W2s  = ts + 8192;     // 8192
    float* hsf  = ts + 16384;    // 4*64
    float* t1f  = ts + 16640;    // 4*128
    float* redf = ts + 17152;    // 4*2*2
    float* red2 = ts + 17168;    // 4*2

    const int tid = threadIdx.x;
    const int base = blockIdx.x * 4;

    for (int i = tid; i < 2048; i += 256)
        ((float4*)W1s)[i] = ((const float4*)W1)[i];
    for (int i = tid; i < 2048; i += 256)
        ((float4*)W2s)[i] = ((const float4*)W2)[i];
    {
        int tok = tid >> 6, f = tid & 63;
        hsf[tok * 64 + f] = embed[(base + tok) * 64 + f];
    }
    __syncthreads();

    // t1 = relu(h W1 + b1): 512 outputs, 2 per thread
    #pragma unroll
    for (int k = 0; k < 2; k++) {
        int o = tid + k * 256;
        int tok = o >> 7, jj = o & 127;
        float acc = b1[jj];
        #pragma unroll
        for (int i = 0; i < 64; i++)
            acc = fmaf(hsf[tok * 64 + i], W1s[i * 128 + jj], acc);
        t1f[tok * 128 + jj] = fmaxf(acc, 0.f);
    }
    __syncthreads();

    const int tok = tid >> 6, f = tid & 63, wh = (tid >> 5) & 1;

    // ff = t1 W2: 256 outputs, 1 per thread
    float acc = 0.f;
    #pragma unroll
    for (int i = 0; i < 128; i++)
        acc = fmaf(t1f[tok * 128 + i], W2s[i * 64 + f], acc);
    float x = hsf[tok * 64 + f] + acc + b2[f];

    // LN over 64 features (per token: 2 warps)
    {
        float s = x, q = x * x;
        #pragma unroll
        for (int o = 16; o > 0; o >>= 1) {
            s += __shfl_xor_sync(0xffffffffu, s, o);
            q += __shfl_xor_sync(0xffffffffu, q, o);
        }
        if ((tid & 31) == 0) {
            redf[tok * 4 + wh * 2 + 0] = s;
            redf[tok * 4 + wh * 2 + 1] = q;
        }
    }
    __syncthreads();
    float y;
    {
        float S = redf[tok * 4 + 0] + redf[tok * 4 + 2];
        float Q = redf[tok * 4 + 1] + redf[tok * 4 + 3];
        float mu = S * (1.0f / 64.0f);
        float var = Q * (1.0f / 64.0f) - mu * mu;
        y = (x - mu) * rsqrtf(var + LN_EPS) * gamma[f] + beta[f];
        g_tab[(base + tok) * 64 + f] = y;
        float z = y * y;
        #pragma unroll
        for (int o = 16; o > 0; o >>= 1)
            z += __shfl_xor_sync(0xffffffffu, z, o);
        if ((tid & 31) == 0) red2[tok * 2 + wh] = z;
    }
    __syncthreads();
    if (f == 0) {
        float d = red2[tok * 2] + red2[tok * 2 + 1] + D_EPS;
        g_dpos[base + tok] = d;
        g_rpos[base + tok] = 1.0f / d;
    }
}

// ---------------------------------------------------------------------------
// K2: G = Tab Tab^T and TW = Tab @ Wr.
// ---------------------------------------------------------------------------
__global__ __launch_bounds__(64) void gram_kernel(const float* __restrict__ Wr)
{
    __shared__ float T[64][65];
    const int a = blockIdx.x, t = threadIdx.x;
    for (int r = 0; r < 64; r++) T[r][t] = g_tab[r * 64 + t];
    __syncthreads();
    float g = 0.f, tw = 0.f;
    #pragma unroll
    for (int h = 0; h < 64; h++) {
        float av = T[a][h];
        g  = fmaf(av, T[t][h], g);
        tw = fmaf(av, Wr[h * 64 + t], tw);
    }
    g_G[a * 64 + t]  = g;
    g_TW[a * 64 + t] = tw;
}

// ---------------------------------------------------------------------------
// K3: per-chunk prep. Ainv = (I+L)^{-1}; then emit dense token-space mats:
//   Bc'[l][b] = r_l * sum_{m: v_m=b} Ainv[l][m]     (t = Bc' w)
//   Fc[j][l]  = G[j][v_l]                            (w -= Fc t)
// ---------------------------------------------------------------------------
__global__ __launch_bounds__(64) void prep_kernel(const int* __restrict__ seq)
{
    __shared__ int   vtok[64];
    __shared__ float rr[64];
    __shared__ float Lsh[64][65];
    __shared__ float Bsh[64][65];

    const int blk = blockIdx.x;
    const int b = blk >> 5, c = blk & 31;
    const int t = threadIdx.x;
    const int* sq = seq + b * SEQL;

    {
        int i = c * 64 + t;                     // reversed global step index
        int v = (i < 2047) ? sq[2046 - i] : 0;  // step 2047 is pad
        vtok[t] = v;
        rr[t]   = (i < 2047) ? g_rpos[v] : 0.f;
    }
    __syncthreads();

    // L row t (strictly lower): L[t][u] = r_u * G[v_t][v_u]
    {
        const float* gr = g_G + vtok[t] * 64;
        for (int u = 0; u < t; u++)
            Lsh[t][u] = rr[u] * gr[vtok[u]];
    }
    __syncthreads();

    // forward substitution: thread t owns column t of X = (I+L)^{-1}
    float X[64];
    #pragma unroll
    for (int i2 = 0; i2 < 64; i2++) X[i2] = (i2 == t) ? 1.f : 0.f;
    #pragma unroll
    for (int u = 0; u < 63; u++) {
        float xu = X[u];
        #pragma unroll
        for (int tt = u + 1; tt < 64; tt++)
            X[tt] = fmaf(-Lsh[tt][u], xu, X[tt]);
    }
    __syncthreads();

    // transpose: Lsh[r][c2] = Ainv[r][c2]
    #pragma unroll
    for (int i2 = 0; i2 < 64; i2++) Lsh[i2][t] = X[i2];
    __syncthreads();

    // Bc row t (owned exclusively): Bsh[t][b2] = sum_{m: v_m=b2} Ainv[t][m]
    for (int b2 = 0; b2 < 64; b2++) Bsh[t][b2] = 0.f;
    for (int m = 0; m < 64; m++) Bsh[t][vtok[m]] += Lsh[t][m];
    __syncthreads();      // everyone done with Lsh (Ainv)

    // stage G into Lsh (coalesced), then emit Bc' and Fc
    for (int idx = t; idx < 4096; idx += 64)
        Lsh[idx >> 6][idx & 63] = g_G[idx];
    __syncthreads();

    {
        float* dstB = g_BF + (size_t)blk * 8192 + t * 64;
        float rt = rr[t];
        #pragma unroll
        for (int b4 = 0; b4 < 16; b4++) {
            float4 v = make_float4(rt * Bsh[t][4*b4+0], rt * Bsh[t][4*b4+1],
                                   rt * Bsh[t][4*b4+2], rt * Bsh[t][4*b4+3]);
            ((float4*)dstB)[b4] = v;
        }
        float* dstF = g_BF + (size_t)blk * 8192 + 4096 + t * 64;
        #pragma unroll
        for (int l4 = 0; l4 < 16; l4++) {
            float4 v = make_float4(Lsh[t][vtok[4*l4+0]], Lsh[t][vtok[4*l4+1]],
                                   Lsh[t][vtok[4*l4+2]], Lsh[t][vtok[4*l4+3]]);
            ((float4*)dstF)[l4] = v;
        }
    }
}

// ---------------------------------------------------------------------------
// K4: chain. 1 block/batch, 256 threads = 64 rows x 4 lanes.
// BF streamed by cp.async (distance 2, 3 buffers, stride-68 rows).
// Per chunk (2 barriers): t = Bc' w  (-> tall);  w -= Fc t.
// Post: beta[a] = d_a * sum_{v_i=a} t_i; head -> out.
// ---------------------------------------------------------------------------
#define ASTRIDE  68
#define BF_BUF   (128 * ASTRIDE)    // 8704 floats per buffered chunk
#define OFF_BF   0                  // 3*8704 = 26112
#define OFF_TALL 26112              // 2048
#define OFF_W    28160              // 64
#define OFF_VB   28224              // 512 floats = 2048 uchar
#define OFF_PART 28736              // 256
#define OFF_BET  28992              // 64
#define OFF_HED  29056              // 64
#define SMEM_FLOATS 29120
#define SMEM_BYTES  (SMEM_FLOATS * 4)

__global__ __launch_bounds__(256) void chain_kernel(
    const int* __restrict__ seq,
    const float* __restrict__ br, const float* __restrict__ Wo,
    const float* __restrict__ bo, float* __restrict__ out)
{
    extern __shared__ float sm[];
    float* tall = sm + OFF_TALL;
    float* wsh  = sm + OFF_W;
    unsigned char* vb = (unsigned char*)(sm + OFF_VB);
    float* part = sm + OFF_PART;
    float* betash = sm + OFF_BET;
    float* hed  = sm + OFF_HED;

    const int b = blockIdx.x, tid = threadIdx.x;
    const int j = tid >> 2, q = tid & 3;
    const int* sq = seq + b * SEQL;
    const float* BFgl = g_BF + (size_t)b * NCHUNK * 8192;

    auto issue_chunk = [&](int c) {
        float* buf = sm + OFF_BF + (c % 3) * BF_BUF;
        const float* src = BFgl + (size_t)c * 8192;
        #pragma unroll
        for (int k = 0; k < 8; k++) {
            int s = tid + k * 256;
            int row = s >> 4, c16 = s & 15;
            uint32_t sa = (uint32_t)__cvta_generic_to_shared(
                              buf + row * ASTRIDE + c16 * 4);
            cp_async16(sa, src + row * 64 + c16 * 4);
        }
    };

    issue_chunk(0); cp_commit();
    issue_chunk(1); cp_commit();

    // stage token stream + w0
    for (int i = tid; i < SEQL; i += 256) {
        int v = (i < 2047) ? sq[2046 - i] : 0;
        vb[i] = (unsigned char)v;
    }
    if (tid < 64) wsh[tid] = g_G[tid * 64 + sq[SEQL - 1]];

    for (int c = 0; c < NCHUNK; c++) {
        cp_wait1();
        __syncthreads();          // chunk c staged; prev w-update visible
        if (c + 2 < NCHUNK) issue_chunk(c + 2);
        cp_commit();

        const float* buf = sm + OFF_BF + (c % 3) * BF_BUF;

        // --- phase 1: t_j = (Bc' w)_j  -> tall[c*64+j] ---
        {
            const float* ab = buf + j * ASTRIDE + q * 16;
            const float4* pv = (const float4*)(wsh + q * 16);
            float4 a0 = *(const float4*)(ab + 0);
            float4 a1 = *(const float4*)(ab + 4);
            float4 a2 = *(const float4*)(ab + 8);
            float4 a3 = *(const float4*)(ab + 12);
            float4 p0 = pv[0], p1 = pv[1], p2 = pv[2], p3 = pv[3];
            float u0 = fmaf(a0.x, p0.x, a0.y * p0.y);
            u0 = fmaf(a0.z, p0.z, u0); u0 = fmaf(a0.w, p0.w, u0);
            float u1 = fmaf(a1.x, p1.x, a1.y * p1.y);
            u1 = fmaf(a1.z, p1.z, u1); u1 = fmaf(a1.w, p1.w, u1);
            float u2 = fmaf(a2.x, p2.x, a2.y * p2.y);
            u2 = fmaf(a2.z, p2.z, u2); u2 = fmaf(a2.w, p2.w, u2);
            float u3 = fmaf(a3.x, p3.x, a3.y * p3.y);
            u3 = fmaf(a3.z, p3.z, u3); u3 = fmaf(a3.w, p3.w, u3);
            float sv = (u0 + u1) + (u2 + u3);
            sv += __shfl_xor_sync(0xffffffffu, sv, 1);
            sv += __shfl_xor_sync(0xffffffffu, sv, 2);
            if (q == 0) tall[c * 64 + j] = sv;
        }
        __syncthreads();

        // --- phase 2: w_j -= (Fc t)_j ---
        {
            const float* fb = buf + (64 + j) * ASTRIDE + q * 16;
            const float4* tv = (const float4*)(tall + c * 64 + q * 16);
            float4 g0 = *(const float4*)(fb + 0);
            float4 g1 = *(const float4*)(fb + 4);
            float4 g2 = *(const float4*)(fb + 8);
            float4 g3 = *(const float4*)(fb + 12);
            float4 t0 = tv[0], t1 = tv[1], t2 = tv[2], t3 = tv[3];
            float u0 = fmaf(g0.x, t0.x, g0.y * t0.y);
            u0 = fmaf(g0.z, t0.z, u0); u0 = fmaf(g0.w, t0.w, u0);
            float u1 = fmaf(g1.x, t1.x, g1.y * t1.y);
            u1 = fmaf(g1.z, t1.z, u1); u1 = fmaf(g1.w, t1.w, u1);
            float u2 = fmaf(g2.x, t2.x, g2.y * t2.y);
            u2 = fmaf(g2.z, t2.z, u2); u2 = fmaf(g2.w, t2.w, u2);
            float u3 = fmaf(g3.x, t3.x, g3.y * t3.y);
            u3 = fmaf(g3.z, t3.z, u3); u3 = fmaf(g3.w, t3.w, u3);
            float du = (u0 + u1) + (u2 + u3);
            du += __shfl_xor_sync(0xffffffffu, du, 1);
            du += __shfl_xor_sync(0xffffffffu, du, 2);
            if (q == 0) wsh[j] -= du;
        }
    }
    __syncthreads();

    // beta partials from tall (deterministic gather)
    {
        const int a = tid & 63, qd = tid >> 6;
        float p = 0.f;
        for (int c = qd; c < NCHUNK; c += 4) {
            const float* tr = tall + c * 64;
            const unsigned char* vr = vb + c * 64;
            #pragma unroll 4
            for (int l0 = 0; l0 < 64; l0 += 4) {
                uchar4 vq4 = *(const uchar4*)(vr + l0);
                float4 tv = *(const float4*)(tr + l0);
                if (vq4.x == a) p += tv.x;
                if (vq4.y == a) p += tv.y;
                if (vq4.z == a) p += tv.z;
                if (vq4.w == a) p += tv.w;
            }
        }
        part[qd * 64 + a] = p;
    }
    __syncthreads();
    if (tid < 64)
        betash[tid] = (part[tid] + part[64 + tid] + part[128 + tid]
                       + part[192 + tid]) * g_dpos[tid];
    __syncthreads();

    // head: out = (beta @ TW + br) @ Wo + bo
    if (tid < 64) {
        float acc = br[tid];
        #pragma unroll
        for (int a = 0; a < 64; a++)
            acc = fmaf(betash[a], g_TW[a * 64 + tid], acc);
        hed[tid] = acc;
    }
    __syncthreads();
    if (tid < 64) {
        float o = bo[tid];
        #pragma unroll
        for (int k = 0; k < 64; k++)
            o = fmaf(hed[k], Wo[k * 64 + tid], o);
        out[b * 64 + tid] = o;
    }
}

// ---------------------------------------------------------------------------
extern "C" void kernel_launch(void* const* d_in, const int* in_sizes, int n_in,
                              void* d_out, int out_size)
{
    const int*   seq   = (const int*)d_in[0];
    const float* embed = (const float*)d_in[1];
    const float* W1    = (const float*)d_in[2];
    const float* b1    = (const float*)d_in[3];
    const float* W2    = (const float*)d_in[4];
    const float* b2    = (const float*)d_in[5];
    const float* gamma = (const float*)d_in[6];
    const float* beta  = (const float*)d_in[7];
    const float* Wr    = (const float*)d_in[8];
    const float* br    = (const float*)d_in[9];
    const float* Wo    = (const float*)d_in[10];
    const float* bo    = (const float*)d_in[11];
    float* out = (float*)d_out;

    cudaFuncSetAttribute(table_kernel,
                         cudaFuncAttributeMaxDynamicSharedMemorySize,
                         TBL_SMEM_BYTES);
    cudaFuncSetAttribute(chain_kernel,
                         cudaFuncAttributeMaxDynamicSharedMemorySize,
                         SMEM_BYTES);

    table_kernel<<<16, 256, TBL_SMEM_BYTES>>>(embed, W1, b1, W2, b2, gamma, beta);
    gram_kernel<<<64, 64>>>(Wr);
    prep_kernel<<<BATCH * NCHUNK, 64>>>(seq);
    chain_kernel<<<BATCH, 256, SMEM_BYTES>>>(seq, br, Wo, bo, out);
}

// round 11
// speedup vs baseline: 1.1301x; 1.1301x over previous
#include <cuda_runtime.h>
#include <cstdint>

#define LN_EPS 1e-5f
#define D_EPS  1e-6f
#define BATCH  16
#define SEQL   2048
#define NCHUNK 32           // 32 chunks x 64 steps = 2048 (2047 real + 1 pad)

// Scratch
__device__ float g_tab[64 * 64];
__device__ float g_G[64 * 64];                     // Gram
__device__ float g_TW[64 * 64];                    // Tab @ Wr
__device__ float g_rpos[64];                       // 1/(||tab||^2 + eps)
__device__ float g_dpos[64];                       // (||tab||^2 + eps)
// per chunk: token-space C (64x64): z = C w drives both beta and w-update
__device__ float g_C[BATCH * NCHUNK * 4096];

// ---------------------------------------------------------------------------
__device__ __forceinline__ void cp_async16(uint32_t saddr, const void* gaddr) {
    asm volatile("cp.async.cg.shared.global [%0], [%1], 16;"
                 :: "r"(saddr), "l"(gaddr));
}
__device__ __forceinline__ void cp_commit() {
    asm volatile("cp.async.commit_group;");
}
__device__ __forceinline__ void cp_wait1() {
    asm volatile("cp.async.wait_group 1;");
}

// ---------------------------------------------------------------------------
// K1: per-token table, 16 blocks x 256 threads x 4 tokens, weights in smem.
// ---------------------------------------------------------------------------
#define TBL_SMEM_FLOATS 17184
#define TBL_SMEM_BYTES  (TBL_SMEM_FLOATS * 4)

__global__ __launch_bounds__(256) void table_kernel(
    const float* __restrict__ embed, const float* __restrict__ W1,
    const float* __restrict__ b1, const float* __restrict__ W2,
    const float* __restrict__ b2, const float* __restrict__ gamma,
    const float* __restrict__ beta)
{
    extern __shared__ float ts[];
    float* W1s  = ts;            // 8192
    float* W2s  = ts + 8192;     // 8192
    float* hsf  = ts + 16384;    // 4*64
    float* t1f  = ts + 16640;    // 4*128
    float* redf = ts + 17152;    // 4*2*2
    float* red2 = ts + 17168;    // 4*2

    const int tid = threadIdx.x;
    const int base = blockIdx.x * 4;

    for (int i = tid; i < 2048; i += 256)
        ((float4*)W1s)[i] = ((const float4*)W1)[i];
    for (int i = tid; i < 2048; i += 256)
        ((float4*)W2s)[i] = ((const float4*)W2)[i];
    {
        int tok = tid >> 6, f = tid & 63;
        hsf[tok * 64 + f] = embed[(base + tok) * 64 + f];
    }
    __syncthreads();

    #pragma unroll
    for (int k = 0; k < 2; k++) {
        int o = tid + k * 256;
        int tok = o >> 7, jj = o & 127;
        float acc = b1[jj];
        #pragma unroll
        for (int i = 0; i < 64; i++)
            acc = fmaf(hsf[tok * 64 + i], W1s[i * 128 + jj], acc);
        t1f[tok * 128 + jj] = fmaxf(acc, 0.f);
    }
    __syncthreads();

    const int tok = tid >> 6, f = tid & 63, wh = (tid >> 5) & 1;

    float acc = 0.f;
    #pragma unroll
    for (int i = 0; i < 128; i++)
        acc = fmaf(t1f[tok * 128 + i], W2s[i * 64 + f], acc);
    float x = hsf[tok * 64 + f] + acc + b2[f];

    {
        float s = x, q = x * x;
        #pragma unroll
        for (int o = 16; o > 0; o >>= 1) {
            s += __shfl_xor_sync(0xffffffffu, s, o);
            q += __shfl_xor_sync(0xffffffffu, q, o);
        }
        if ((tid & 31) == 0) {
            redf[tok * 4 + wh * 2 + 0] = s;
            redf[tok * 4 + wh * 2 + 1] = q;
        }
    }
    __syncthreads();
    float y;
    {
        float S = redf[tok * 4 + 0] + redf[tok * 4 + 2];
        float Q = redf[tok * 4 + 1] + redf[tok * 4 + 3];
        float mu = S * (1.0f / 64.0f);
        float var = Q * (1.0f / 64.0f) - mu * mu;
        y = (x - mu) * rsqrtf(var + LN_EPS) * gamma[f] + beta[f];
        g_tab[(base + tok) * 64 + f] = y;
        float z = y * y;
        #pragma unroll
        for (int o = 16; o > 0; o >>= 1)
            z += __shfl_xor_sync(0xffffffffu, z, o);
        if ((tid & 31) == 0) red2[tok * 2 + wh] = z;
    }
    __syncthreads();
    if (f == 0) {
        float d = red2[tok * 2] + red2[tok * 2 + 1] + D_EPS;
        g_dpos[base + tok] = d;
        g_rpos[base + tok] = 1.0f / d;
    }
}

// ---------------------------------------------------------------------------
// K2: G = Tab Tab^T and TW = Tab @ Wr.
// ---------------------------------------------------------------------------
__global__ __launch_bounds__(64) void gram_kernel(const float* __restrict__ Wr)
{
    __shared__ float T[64][65];
    const int a = blockIdx.x, t = threadIdx.x;
    for (int r = 0; r < 64; r++) T[r][t] = g_tab[r * 64 + t];
    __syncthreads();
    float g = 0.f, tw = 0.f;
    #pragma unroll
    for (int h = 0; h < 64; h++) {
        float av = T[a][h];
        g  = fmaf(av, T[t][h], g);
        tw = fmaf(av, Wr[h * 64 + t], tw);
    }
    g_G[a * 64 + t]  = g;
    g_TW[a * 64 + t] = tw;
}

// ---------------------------------------------------------------------------
// K3: per-chunk prep. Ainv = (I+L)^{-1}; emit token-space
//   C[a][b] = sum_{l: v_l=a} r_l * sum_{m: v_m=b} Ainv[l][m]
// Csh aliases Lsh (Ainv dead once Bsh built).
// ---------------------------------------------------------------------------
__global__ __launch_bounds__(64) void prep_kernel(const int* __restrict__ seq)
{
    __shared__ int   vtok[64];
    __shared__ float rr[64];
    __shared__ float Lsh[64 * 65];     // L -> Ainv -> (aliased) Csh
    __shared__ float Bsh[64 * 65];

    const int blk = blockIdx.x;
    const int b = blk >> 5, c = blk & 31;
    const int t = threadIdx.x;
    const int* sq = seq + b * SEQL;

    {
        int i = c * 64 + t;                     // reversed global step index
        int v = (i < 2047) ? sq[2046 - i] : 0;  // step 2047 is pad
        vtok[t] = v;
        rr[t]   = (i < 2047) ? g_rpos[v] : 0.f;
    }
    __syncthreads();

    // L row t (strictly lower): L[t][u] = r_u * G[v_t][v_u]
    {
        const float* gr = g_G + vtok[t] * 64;
        for (int u = 0; u < t; u++)
            Lsh[t * 65 + u] = rr[u] * gr[vtok[u]];
    }
    __syncthreads();

    // forward substitution: thread t owns column t of X = (I+L)^{-1}
    float X[64];
    #pragma unroll
    for (int i2 = 0; i2 < 64; i2++) X[i2] = (i2 == t) ? 1.f : 0.f;
    #pragma unroll
    for (int u = 0; u < 63; u++) {
        float xu = X[u];
        #pragma unroll
        for (int tt = u + 1; tt < 64; tt++)
            X[tt] = fmaf(-Lsh[tt * 65 + u], xu, X[tt]);
    }
    __syncthreads();

    // Lsh <- Ainv (row r, col t)
    #pragma unroll
    for (int i2 = 0; i2 < 64; i2++) Lsh[i2 * 65 + t] = X[i2];
    __syncthreads();

    // Bsh row t: Bsh[t][b2] = sum_{m: v_m=b2} Ainv[t][m]
    for (int b2 = 0; b2 < 64; b2++) Bsh[t * 65 + b2] = 0.f;
    for (int m = 0; m < 64; m++) Bsh[t * 65 + vtok[m]] += Lsh[t * 65 + m];
    __syncthreads();       // Lsh (Ainv) now dead -> reuse as Csh

    float* Csh = Lsh;
    for (int a = 0; a < 64; a++) Csh[a * 65 + t] = 0.f;
    __syncthreads();
    // column t owned exclusively: C[a][t] += r_l * Bsh[l][t] for a=v_l
    for (int l = 0; l < 64; l++)
        Csh[vtok[l] * 65 + t] += rr[l] * Bsh[l * 65 + t];
    __syncthreads();

    // store row t coalesced
    {
        float4* dst = (float4*)(g_C + (size_t)blk * 4096 + t * 64);
        const float* src = Csh + t * 65;
        #pragma unroll
        for (int j4 = 0; j4 < 16; j4++)
            dst[j4] = make_float4(src[4*j4], src[4*j4+1],
                                  src[4*j4+2], src[4*j4+3]);
    }
}

// ---------------------------------------------------------------------------
// K4: chain. 1 block/batch, 256 threads = 64 rows x 4 lanes.
// C streamed by cp.async (distance 2, 3 buffers, stride-68 rows); G resident.
// Per chunk (2 barriers): z = C w (zacc += z, -> zsh);  w -= G z.
// Post: beta = d .* zacc; head -> out.
// ---------------------------------------------------------------------------
#define ASTRIDE  68
#define OFF_GS   0                  // 64*68 = 4352
#define OFF_CB   4352               // 3*64*68 = 13056 -> 17408
#define OFF_W    17408              // 64
#define OFF_Z    17472              // 64
#define OFF_BET  17536              // 64
#define OFF_HED  17600              // 64
#define SMEM_FLOATS 17664
#define SMEM_BYTES  (SMEM_FLOATS * 4)

__global__ __launch_bounds__(256) void chain_kernel(
    const int* __restrict__ seq,
    const float* __restrict__ br, const float* __restrict__ Wo,
    const float* __restrict__ bo, float* __restrict__ out)
{
    extern __shared__ float sm[];
    float* Gs   = sm + OFF_GS;
    float* wsh  = sm + OFF_W;
    float* zsh  = sm + OFF_Z;
    float* betash = sm + OFF_BET;
    float* hed  = sm + OFF_HED;

    const int b = blockIdx.x, tid = threadIdx.x;
    const int j = tid >> 2, q = tid & 3;
    const int* sq = seq + b * SEQL;
    const float* Cgl = g_C + (size_t)b * NCHUNK * 4096;

    auto issue_chunk = [&](int c) {
        float* buf = sm + OFF_CB + (c % 3) * (64 * ASTRIDE);
        const float* src = Cgl + (size_t)c * 4096;
        #pragma unroll
        for (int k = 0; k < 4; k++) {
            int s = tid + k * 256;
            int row = s >> 4, c16 = s & 15;
            uint32_t sa = (uint32_t)__cvta_generic_to_shared(
                              buf + row * ASTRIDE + c16 * 4);
            cp_async16(sa, src + row * 64 + c16 * 4);
        }
    };

    issue_chunk(0); cp_commit();
    issue_chunk(1); cp_commit();

    // stage G (stride 68) + w0
    for (int idx = tid; idx < 4096; idx += 256)
        Gs[(idx >> 6) * ASTRIDE + (idx & 63)] = g_G[idx];
    if (tid < 64) wsh[tid] = g_G[tid * 64 + sq[SEQL - 1]];

    float zacc = 0.f;     // meaningful on q==0 lanes (row j)

    for (int c = 0; c < NCHUNK; c++) {
        cp_wait1();
        __syncthreads();          // chunk c staged; prev w-update visible
        if (c + 2 < NCHUNK) issue_chunk(c + 2);
        cp_commit();

        const float* buf = sm + OFF_CB + (c % 3) * (64 * ASTRIDE);

        // --- phase 1: z_j = (C w)_j ---
        {
            const float* ab = buf + j * ASTRIDE + q * 16;
            const float4* pv = (const float4*)(wsh + q * 16);
            float4 a0 = *(const float4*)(ab + 0);
            float4 a1 = *(const float4*)(ab + 4);
            float4 a2 = *(const float4*)(ab + 8);
            float4 a3 = *(const float4*)(ab + 12);
            float4 p0 = pv[0], p1 = pv[1], p2 = pv[2], p3 = pv[3];
            float u0 = fmaf(a0.x, p0.x, a0.y * p0.y);
            u0 = fmaf(a0.z, p0.z, u0); u0 = fmaf(a0.w, p0.w, u0);
            float u1 = fmaf(a1.x, p1.x, a1.y * p1.y);
            u1 = fmaf(a1.z, p1.z, u1); u1 = fmaf(a1.w, p1.w, u1);
            float u2 = fmaf(a2.x, p2.x, a2.y * p2.y);
            u2 = fmaf(a2.z, p2.z, u2); u2 = fmaf(a2.w, p2.w, u2);
            float u3 = fmaf(a3.x, p3.x, a3.y * p3.y);
            u3 = fmaf(a3.z, p3.z, u3); u3 = fmaf(a3.w, p3.w, u3);
            float sv = (u0 + u1) + (u2 + u3);
            sv += __shfl_xor_sync(0xffffffffu, sv, 1);
            sv += __shfl_xor_sync(0xffffffffu, sv, 2);
            if (q == 0) { zsh[j] = sv; zacc += sv; }
        }
        __syncthreads();

        // --- phase 2: w_j -= (G z)_j ---
        {
            const float* gr = Gs + j * ASTRIDE + q * 16;
            const float4* zv = (const float4*)(zsh + q * 16);
            float4 g0 = *(const float4*)(gr + 0);
            float4 g1 = *(const float4*)(gr + 4);
            float4 g2 = *(const float4*)(gr + 8);
            float4 g3 = *(const float4*)(gr + 12);
            float4 z0 = zv[0], z1 = zv[1], z2 = zv[2], z3 = zv[3];
            float u0 = fmaf(g0.x, z0.x, g0.y * z0.y);
            u0 = fmaf(g0.z, z0.z, u0); u0 = fmaf(g0.w, z0.w, u0);
            float u1 = fmaf(g1.x, z1.x, g1.y * z1.y);
            u1 = fmaf(g1.z, z1.z, u1); u1 = fmaf(g1.w, z1.w, u1);
            float u2 = fmaf(g2.x, z2.x, g2.y * z2.y);
            u2 = fmaf(g2.z, z2.z, u2); u2 = fmaf(g2.w, z2.w, u2);
            float u3 = fmaf(g3.x, z3.x, g3.y * z3.y);
            u3 = fmaf(g3.z, z3.z, u3); u3 = fmaf(g3.w, z3.w, u3);
            float du = (u0 + u1) + (u2 + u3);
            du += __shfl_xor_sync(0xffffffffu, du, 1);
            du += __shfl_xor_sync(0xffffffffu, du, 2);
            if (q == 0) wsh[j] -= du;
        }
    }

    // beta[j] = zacc * d_j
    if (q == 0) betash[j] = zacc * g_dpos[j];
    __syncthreads();

    // head: out = (beta @ TW + br) @ Wo + bo
    if (tid < 64) {
        float acc = br[tid];
        #pragma unroll
        for (int a = 0; a < 64; a++)
            acc = fmaf(betash[a], g_TW[a * 64 + tid], acc);
        hed[tid] = acc;
    }
    __syncthreads();
    if (tid < 64) {
        float o = bo[tid];
        #pragma unroll
        for (int k = 0; k < 64; k++)
            o = fmaf(hed[k], Wo[k * 64 + tid], o);
        out[b * 64 + tid] = o;
    }
}

// ---------------------------------------------------------------------------
extern "C" void kernel_launch(void* const* d_in, const int* in_sizes, int n_in,
                              void* d_out, int out_size)
{
    const int*   seq   = (const int*)d_in[0];
    const float* embed = (const float*)d_in[1];
    const float* W1    = (const float*)d_in[2];
    const float* b1    = (const float*)d_in[3];
    const float* W2    = (const float*)d_in[4];
    const float* b2    = (const float*)d_in[5];
    const float* gamma = (const float*)d_in[6];
    const float* beta  = (const float*)d_in[7];
    const float* Wr    = (const float*)d_in[8];
    const float* br    = (const float*)d_in[9];
    const float* Wo    = (const float*)d_in[10];
    const float* bo    = (const float*)d_in[11];
    float* out = (float*)d_out;

    cudaFuncSetAttribute(table_kernel,
                         cudaFuncAttributeMaxDynamicSharedMemorySize,
                         TBL_SMEM_BYTES);
    cudaFuncSetAttribute(chain_kernel,
                         cudaFuncAttributeMaxDynamicSharedMemorySize,
                         SMEM_BYTES);

    table_kernel<<<16, 256, TBL_SMEM_BYTES>>>(embed, W1, b1, W2, b2, gamma, beta);
    gram_kernel<<<64, 64>>>(Wr);
    prep_kernel<<<BATCH * NCHUNK, 64>>>(seq);
    chain_kernel<<<BATCH, 256, SMEM_BYTES>>>(seq, br, Wo, bo, out);
}